// round 9
// baseline (speedup 1.0000x reference)
#include <cuda_runtime.h>

#define S_LEN 2048
#define E_DIM 1024
#define NHEAD 16
#define DHEAD 64
#define BATCH 2
#define MROWS 4096   // BATCH * S_LEN
#define KDIM  1024

// ---------------- scratch (allocation-free) ----------------
__device__ float g_Qp[BATCH * NHEAD * S_LEN * DHEAD];  // [b][h][s][d]
__device__ float g_Kp[BATCH * NHEAD * S_LEN * DHEAD];
__device__ float g_Vp[BATCH * NHEAD * S_LEN * DHEAD];
__device__ float g_ctx[BATCH * S_LEN * E_DIM];         // [b][s][e]

// =====================================================================
// SGEMM: out = X[4096,1024] @ W[1024, n-slice] + bias
// 128x128 block tile, BK=16, 256 threads, 8x8 microtile, double-buffered.
// mode 0: write head-split layout [b][h][s][d]; mode 1: plain row-major.
// =====================================================================
__global__ __launch_bounds__(256, 2) void sgemm_kernel(
    const float* __restrict__ X, const float* __restrict__ W, int ldw,
    const float* __restrict__ bias, float* __restrict__ out, int mode)
{
    __shared__ float sA[2][16 * 132];   // sA[k][m], padded stride 132
    __shared__ float sB[2][16 * 128];   // sB[k][n]

    const int tid = threadIdx.x;
    const int tx = tid & 15, ty = tid >> 4;
    const int m0 = blockIdx.y << 7;
    const int n0 = blockIdx.x << 7;

    // A loader: 512 float4 over 256 threads (2 each). idx -> row=idx>>2, kcol4=(idx&3)*4
    const int aR0 = tid >> 2,         aC0 = (tid & 3) << 2;
    const int aR1 = (tid + 256) >> 2, aC1 = aC0;           // (tid+256)&3 == tid&3
    // B loader: idx -> krow=idx>>5, ncol4=(idx&31)*4
    const int bR0 = tid >> 5,         bC0 = (tid & 31) << 2;
    const int bR1 = bR0 + 8,          bC1 = bC0;

    float acc[8][8];
    #pragma unroll
    for (int i = 0; i < 8; i++)
        #pragma unroll
        for (int j = 0; j < 8; j++) acc[i][j] = 0.f;

    float4 ra0, ra1, rb0, rb1;
    // prologue: tile 0
    ra0 = *reinterpret_cast<const float4*>(&X[(m0 + aR0) * KDIM + aC0]);
    ra1 = *reinterpret_cast<const float4*>(&X[(m0 + aR1) * KDIM + aC1]);
    rb0 = *reinterpret_cast<const float4*>(&W[bR0 * ldw + n0 + bC0]);
    rb1 = *reinterpret_cast<const float4*>(&W[bR1 * ldw + n0 + bC1]);
    {
        float* p0 = &sA[0][aC0 * 132 + aR0];
        p0[0] = ra0.x; p0[132] = ra0.y; p0[264] = ra0.z; p0[396] = ra0.w;
        float* p1 = &sA[0][aC1 * 132 + aR1];
        p1[0] = ra1.x; p1[132] = ra1.y; p1[264] = ra1.z; p1[396] = ra1.w;
        *reinterpret_cast<float4*>(&sB[0][bR0 * 128 + bC0]) = rb0;
        *reinterpret_cast<float4*>(&sB[0][bR1 * 128 + bC1]) = rb1;
    }
    __syncthreads();

    int buf = 0;
    const int NSTEPS = KDIM / 16;
    for (int s = 0; s < NSTEPS; s++) {
        if (s + 1 < NSTEPS) {
            const int kn = (s + 1) << 4;
            ra0 = *reinterpret_cast<const float4*>(&X[(m0 + aR0) * KDIM + kn + aC0]);
            ra1 = *reinterpret_cast<const float4*>(&X[(m0 + aR1) * KDIM + kn + aC1]);
            rb0 = *reinterpret_cast<const float4*>(&W[(kn + bR0) * ldw + n0 + bC0]);
            rb1 = *reinterpret_cast<const float4*>(&W[(kn + bR1) * ldw + n0 + bC1]);
        }
        const float* pa = &sA[buf][ty << 3];
        const float* pb = &sB[buf][tx << 3];
        #pragma unroll 8
        for (int kk = 0; kk < 16; kk++) {
            float4 a0 = *reinterpret_cast<const float4*>(&pa[kk * 132]);
            float4 a1 = *reinterpret_cast<const float4*>(&pa[kk * 132 + 4]);
            float4 b0 = *reinterpret_cast<const float4*>(&pb[kk * 128]);
            float4 b1 = *reinterpret_cast<const float4*>(&pb[kk * 128 + 4]);
            float av[8] = {a0.x, a0.y, a0.z, a0.w, a1.x, a1.y, a1.z, a1.w};
            float bv[8] = {b0.x, b0.y, b0.z, b0.w, b1.x, b1.y, b1.z, b1.w};
            #pragma unroll
            for (int i = 0; i < 8; i++)
                #pragma unroll
                for (int j = 0; j < 8; j++)
                    acc[i][j] = fmaf(av[i], bv[j], acc[i][j]);
        }
        if (s + 1 < NSTEPS) {
            const int nb = buf ^ 1;
            float* p0 = &sA[nb][aC0 * 132 + aR0];
            p0[0] = ra0.x; p0[132] = ra0.y; p0[264] = ra0.z; p0[396] = ra0.w;
            float* p1 = &sA[nb][aC1 * 132 + aR1];
            p1[0] = ra1.x; p1[132] = ra1.y; p1[264] = ra1.z; p1[396] = ra1.w;
            *reinterpret_cast<float4*>(&sB[nb][bR0 * 128 + bC0]) = rb0;
            *reinterpret_cast<float4*>(&sB[nb][bR1 * 128 + bC1]) = rb1;
        }
        __syncthreads();
        buf ^= 1;
    }

    // epilogue: bias + store
    #pragma unroll
    for (int i = 0; i < 8; i++) {
        const int m  = m0 + (ty << 3) + i;
        const int bb = m >> 11;          // / S_LEN
        const int sq = m & (S_LEN - 1);
        #pragma unroll
        for (int j = 0; j < 8; j++) {
            const int n = n0 + (tx << 3) + j;
            const float val = acc[i][j] + bias[n];
            if (mode == 0) {
                const int hh = n >> 6, dd = n & 63;
                out[((bb * NHEAD + hh) * S_LEN + sq) * DHEAD + dd] = val;
            } else {
                out[m * E_DIM + n] = val;
            }
        }
    }
}

// =====================================================================
// Flash attention: grid (S/64, H, B), 256 threads, 64x64 tiles, D=64.
// Online softmax, scores never hit gmem. Dynamic smem = 4 * 64*68 floats.
// =====================================================================
#define PADW 68
#define ATTN_SMEM (4 * 64 * PADW * (int)sizeof(float))

__global__ __launch_bounds__(256) void attn_kernel(
    const float* __restrict__ Qp, const float* __restrict__ Kp,
    const float* __restrict__ Vp, const int* __restrict__ mask,
    float* __restrict__ ctx)
{
    extern __shared__ float smem[];
    float* Qt = smem;                 // [d][q]  stride PADW
    float* Kt = smem + 64 * PADW;     // [d][j]
    float* Vs = smem + 2 * 64 * PADW; // [j][d]
    float* Ps = smem + 3 * 64 * PADW; // [j][i]

    const int tid = threadIdx.x;
    const int tx = tid & 15, ty = tid >> 4;
    const int q0 = blockIdx.x << 6;
    const int h  = blockIdx.y, b = blockIdx.z;
    const int base = ((b * NHEAD + h) * S_LEN) * DHEAD;

    // stage Q transposed (once per block)
    {
        const int d = tid & 63, sg = (tid >> 6) << 4;
        #pragma unroll
        for (int blk = 0; blk < 16; blk += 4) {
            const int s = q0 + sg + blk;
            float t0 = Qp[base + (s + 0) * DHEAD + d];
            float t1 = Qp[base + (s + 1) * DHEAD + d];
            float t2 = Qp[base + (s + 2) * DHEAD + d];
            float t3 = Qp[base + (s + 3) * DHEAD + d];
            *reinterpret_cast<float4*>(&Qt[d * PADW + sg + blk]) = make_float4(t0, t1, t2, t3);
        }
    }

    float o[4][4];
    #pragma unroll
    for (int i = 0; i < 4; i++) { o[i][0] = o[i][1] = o[i][2] = o[i][3] = 0.f; }
    float mrow[4] = {-1e30f, -1e30f, -1e30f, -1e30f};
    float lrow[4] = {0.f, 0.f, 0.f, 0.f};

    for (int kt = 0; kt < S_LEN / 64; kt++) {
        const int k0 = kt << 6;
        __syncthreads();  // protect Kt/Vs/Ps from previous iteration readers

        // stage K transposed
        {
            const int d = tid & 63, sg = (tid >> 6) << 4;
            #pragma unroll
            for (int blk = 0; blk < 16; blk += 4) {
                const int s = k0 + sg + blk;
                float t0 = Kp[base + (s + 0) * DHEAD + d];
                float t1 = Kp[base + (s + 1) * DHEAD + d];
                float t2 = Kp[base + (s + 2) * DHEAD + d];
                float t3 = Kp[base + (s + 3) * DHEAD + d];
                *reinterpret_cast<float4*>(&Kt[d * PADW + sg + blk]) = make_float4(t0, t1, t2, t3);
            }
        }
        // stage V natural
        #pragma unroll
        for (int r = 0; r < 4; r++) {
            const int idx = tid + (r << 8);
            const int srow = idx >> 4, c = (idx & 15) << 2;
            float4 vv = *reinterpret_cast<const float4*>(&Vp[base + (k0 + srow) * DHEAD + c]);
            *reinterpret_cast<float4*>(&Vs[srow * PADW + c]) = vv;
        }
        __syncthreads();

        // S = Q @ K^T  (4x4 microtile per thread)
        float sa[4][4];
        #pragma unroll
        for (int i = 0; i < 4; i++) { sa[i][0] = sa[i][1] = sa[i][2] = sa[i][3] = 0.f; }
        #pragma unroll 8
        for (int kk = 0; kk < 64; kk++) {
            float4 a  = *reinterpret_cast<const float4*>(&Qt[kk * PADW + (ty << 2)]);
            float4 bk = *reinterpret_cast<const float4*>(&Kt[kk * PADW + (tx << 2)]);
            sa[0][0] = fmaf(a.x, bk.x, sa[0][0]); sa[0][1] = fmaf(a.x, bk.y, sa[0][1]);
            sa[0][2] = fmaf(a.x, bk.z, sa[0][2]); sa[0][3] = fmaf(a.x, bk.w, sa[0][3]);
            sa[1][0] = fmaf(a.y, bk.x, sa[1][0]); sa[1][1] = fmaf(a.y, bk.y, sa[1][1]);
            sa[1][2] = fmaf(a.y, bk.z, sa[1][2]); sa[1][3] = fmaf(a.y, bk.w, sa[1][3]);
            sa[2][0] = fmaf(a.z, bk.x, sa[2][0]); sa[2][1] = fmaf(a.z, bk.y, sa[2][1]);
            sa[2][2] = fmaf(a.z, bk.z, sa[2][2]); sa[2][3] = fmaf(a.z, bk.w, sa[2][3]);
            sa[3][0] = fmaf(a.w, bk.x, sa[3][0]); sa[3][1] = fmaf(a.w, bk.y, sa[3][1]);
            sa[3][2] = fmaf(a.w, bk.z, sa[3][2]); sa[3][3] = fmaf(a.w, bk.w, sa[3][3]);
        }

        // mask + scale (1/sqrt(D) = 0.125)
        #pragma unroll
        for (int ii = 0; ii < 4; ii++) {
            const int4 mv = *reinterpret_cast<const int4*>(
                &mask[(q0 + (ty << 2) + ii) * S_LEN + k0 + (tx << 2)]);
            sa[ii][0] = mv.x ? sa[ii][0] * 0.125f : -1e30f;
            sa[ii][1] = mv.y ? sa[ii][1] * 0.125f : -1e30f;
            sa[ii][2] = mv.z ? sa[ii][2] * 0.125f : -1e30f;
            sa[ii][3] = mv.w ? sa[ii][3] * 0.125f : -1e30f;
        }

        // online softmax per row (rows shared across the 16 tx lanes)
        #pragma unroll
        for (int ii = 0; ii < 4; ii++) {
            float tm = fmaxf(fmaxf(sa[ii][0], sa[ii][1]), fmaxf(sa[ii][2], sa[ii][3]));
            tm = fmaxf(tm, __shfl_xor_sync(0xffffffffu, tm, 8));
            tm = fmaxf(tm, __shfl_xor_sync(0xffffffffu, tm, 4));
            tm = fmaxf(tm, __shfl_xor_sync(0xffffffffu, tm, 2));
            tm = fmaxf(tm, __shfl_xor_sync(0xffffffffu, tm, 1));
            const float mn = fmaxf(mrow[ii], tm);
            const float corr = __expf(mrow[ii] - mn);
            mrow[ii] = mn;
            float ps = 0.f;
            #pragma unroll
            for (int jj = 0; jj < 4; jj++) {
                sa[ii][jj] = __expf(sa[ii][jj] - mn);   // masked -> exp(-huge) = 0
                ps += sa[ii][jj];
            }
            ps += __shfl_xor_sync(0xffffffffu, ps, 8);
            ps += __shfl_xor_sync(0xffffffffu, ps, 4);
            ps += __shfl_xor_sync(0xffffffffu, ps, 2);
            ps += __shfl_xor_sync(0xffffffffu, ps, 1);
            lrow[ii] = lrow[ii] * corr + ps;
            o[ii][0] *= corr; o[ii][1] *= corr; o[ii][2] *= corr; o[ii][3] *= corr;
        }

        // store P transposed: Ps[j][i]
        #pragma unroll
        for (int jj = 0; jj < 4; jj++)
            *reinterpret_cast<float4*>(&Ps[((tx << 2) + jj) * PADW + (ty << 2)]) =
                make_float4(sa[0][jj], sa[1][jj], sa[2][jj], sa[3][jj]);
        __syncthreads();

        // O += P @ V
        #pragma unroll 8
        for (int kk = 0; kk < 64; kk++) {
            float4 ap = *reinterpret_cast<const float4*>(&Ps[kk * PADW + (ty << 2)]);
            float4 av = *reinterpret_cast<const float4*>(&Vs[kk * PADW + (tx << 2)]);
            o[0][0] = fmaf(ap.x, av.x, o[0][0]); o[0][1] = fmaf(ap.x, av.y, o[0][1]);
            o[0][2] = fmaf(ap.x, av.z, o[0][2]); o[0][3] = fmaf(ap.x, av.w, o[0][3]);
            o[1][0] = fmaf(ap.y, av.x, o[1][0]); o[1][1] = fmaf(ap.y, av.y, o[1][1]);
            o[1][2] = fmaf(ap.y, av.z, o[1][2]); o[1][3] = fmaf(ap.y, av.w, o[1][3]);
            o[2][0] = fmaf(ap.z, av.x, o[2][0]); o[2][1] = fmaf(ap.z, av.y, o[2][1]);
            o[2][2] = fmaf(ap.z, av.z, o[2][2]); o[2][3] = fmaf(ap.z, av.w, o[2][3]);
            o[3][0] = fmaf(ap.w, av.x, o[3][0]); o[3][1] = fmaf(ap.w, av.y, o[3][1]);
            o[3][2] = fmaf(ap.w, av.z, o[3][2]); o[3][3] = fmaf(ap.w, av.w, o[3][3]);
        }
    }

    // normalize + write ctx in [b][s][e] layout (e = h*64 + d)
    #pragma unroll
    for (int ii = 0; ii < 4; ii++) {
        const float inv = 1.f / lrow[ii];
        const int row = q0 + (ty << 2) + ii;
        float4 w = make_float4(o[ii][0] * inv, o[ii][1] * inv, o[ii][2] * inv, o[ii][3] * inv);
        *reinterpret_cast<float4*>(&ctx[(b * S_LEN + row) * E_DIM + h * DHEAD + (tx << 2)]) = w;
    }
}

// =====================================================================
extern "C" void kernel_launch(void* const* d_in, const int* in_sizes, int n_in,
                              void* d_out, int out_size)
{
    const float* q    = (const float*)d_in[0];
    const float* k    = (const float*)d_in[1];
    const float* v    = (const float*)d_in[2];
    const int*   mask = (const int*)  d_in[3];
    const float* Wqkv = (const float*)d_in[4];
    const float* bqkv = (const float*)d_in[5];
    const float* Wout = (const float*)d_in[6];
    const float* bout = (const float*)d_in[7];
    float* out = (float*)d_out;
    (void)in_sizes; (void)n_in; (void)out_size;

    float *Qp, *Kp, *Vp, *ctx;
    cudaGetSymbolAddress((void**)&Qp,  g_Qp);
    cudaGetSymbolAddress((void**)&Kp,  g_Kp);
    cudaGetSymbolAddress((void**)&Vp,  g_Vp);
    cudaGetSymbolAddress((void**)&ctx, g_ctx);

    cudaFuncSetAttribute(attn_kernel, cudaFuncAttributeMaxDynamicSharedMemorySize, ATTN_SMEM);

    dim3 gg(E_DIM / 128, MROWS / 128);   // (8, 32)
    sgemm_kernel<<<gg, 256>>>(q, Wqkv,             3 * E_DIM, bqkv,             Qp, 0);
    sgemm_kernel<<<gg, 256>>>(k, Wqkv + E_DIM,     3 * E_DIM, bqkv + E_DIM,     Kp, 0);
    sgemm_kernel<<<gg, 256>>>(v, Wqkv + 2 * E_DIM, 3 * E_DIM, bqkv + 2 * E_DIM, Vp, 0);

    attn_kernel<<<dim3(S_LEN / 64, NHEAD, BATCH), 256, ATTN_SMEM>>>(Qp, Kp, Vp, mask, ctx);

    sgemm_kernel<<<gg, 256>>>(ctx, Wout, E_DIM, bout, out, 1);
}

// round 10
// speedup vs baseline: 1.0542x; 1.0542x over previous
#include <cuda_runtime.h>

#define S_LEN 2048
#define E_DIM 1024
#define NHEAD 16
#define DHEAD 64
#define BATCH 2
#define MROWS 4096   // BATCH * S_LEN
#define KDIM  1024

// ---------------- scratch (allocation-free) ----------------
__device__ float g_Qp[BATCH * NHEAD * S_LEN * DHEAD];  // [b][h][s][d]
__device__ float g_Kp[BATCH * NHEAD * S_LEN * DHEAD];
__device__ float g_Vp[BATCH * NHEAD * S_LEN * DHEAD];
__device__ float g_ctx[BATCH * S_LEN * E_DIM];         // [b][s][e]

// =====================================================================
// Fused QKV projection GEMM.
// grid (24, 32): blockIdx.x selects 128-col slab of the 3072-wide Wqkv;
// slice = bx>>3 picks input (q/k/v) and output buffer (Qp/Kp/Vp).
// 128x128 tile, BK=16, 256 threads, 8x8 microtile, double-buffered.
// Output written in head-split layout [b][h][s][d].
// =====================================================================
__global__ __launch_bounds__(256, 2) void sgemm_qkv_kernel(
    const float* __restrict__ q, const float* __restrict__ k,
    const float* __restrict__ v, const float* __restrict__ W,
    const float* __restrict__ bias,
    float* __restrict__ Qp, float* __restrict__ Kp, float* __restrict__ Vp)
{
    __shared__ float sA[2][16 * 132];
    __shared__ float sB[2][16 * 128];

    const int tid = threadIdx.x;
    const int tx = tid & 15, ty = tid >> 4;
    const int m0 = blockIdx.y << 7;
    const int bx = blockIdx.x;
    const int slice = bx >> 3;
    const int n0 = bx << 7;                 // global col into [0,3072)
    const int ldw = 3 * E_DIM;

    const float* X  = (slice == 0) ? q : (slice == 1) ? k : v;
    float* out      = (slice == 0) ? Qp : (slice == 1) ? Kp : Vp;

    const int aR0 = tid >> 2,         aC0 = (tid & 3) << 2;
    const int aR1 = (tid + 256) >> 2, aC1 = aC0;
    const int bR0 = tid >> 5,         bC0 = (tid & 31) << 2;
    const int bR1 = bR0 + 8,          bC1 = bC0;

    float acc[8][8];
    #pragma unroll
    for (int i = 0; i < 8; i++)
        #pragma unroll
        for (int j = 0; j < 8; j++) acc[i][j] = 0.f;

    float4 ra0, ra1, rb0, rb1;
    ra0 = *reinterpret_cast<const float4*>(&X[(m0 + aR0) * KDIM + aC0]);
    ra1 = *reinterpret_cast<const float4*>(&X[(m0 + aR1) * KDIM + aC1]);
    rb0 = *reinterpret_cast<const float4*>(&W[bR0 * ldw + n0 + bC0]);
    rb1 = *reinterpret_cast<const float4*>(&W[bR1 * ldw + n0 + bC1]);
    {
        float* p0 = &sA[0][aC0 * 132 + aR0];
        p0[0] = ra0.x; p0[132] = ra0.y; p0[264] = ra0.z; p0[396] = ra0.w;
        float* p1 = &sA[0][aC1 * 132 + aR1];
        p1[0] = ra1.x; p1[132] = ra1.y; p1[264] = ra1.z; p1[396] = ra1.w;
        *reinterpret_cast<float4*>(&sB[0][bR0 * 128 + bC0]) = rb0;
        *reinterpret_cast<float4*>(&sB[0][bR1 * 128 + bC1]) = rb1;
    }
    __syncthreads();

    int buf = 0;
    const int NSTEPS = KDIM / 16;
    for (int s = 0; s < NSTEPS; s++) {
        if (s + 1 < NSTEPS) {
            const int kn = (s + 1) << 4;
            ra0 = *reinterpret_cast<const float4*>(&X[(m0 + aR0) * KDIM + kn + aC0]);
            ra1 = *reinterpret_cast<const float4*>(&X[(m0 + aR1) * KDIM + kn + aC1]);
            rb0 = *reinterpret_cast<const float4*>(&W[(kn + bR0) * ldw + n0 + bC0]);
            rb1 = *reinterpret_cast<const float4*>(&W[(kn + bR1) * ldw + n0 + bC1]);
        }
        const float* pa = &sA[buf][ty << 3];
        const float* pb = &sB[buf][tx << 3];
        #pragma unroll 8
        for (int kk = 0; kk < 16; kk++) {
            float4 a0 = *reinterpret_cast<const float4*>(&pa[kk * 132]);
            float4 a1 = *reinterpret_cast<const float4*>(&pa[kk * 132 + 4]);
            float4 b0 = *reinterpret_cast<const float4*>(&pb[kk * 128]);
            float4 b1 = *reinterpret_cast<const float4*>(&pb[kk * 128 + 4]);
            float av[8] = {a0.x, a0.y, a0.z, a0.w, a1.x, a1.y, a1.z, a1.w};
            float bv[8] = {b0.x, b0.y, b0.z, b0.w, b1.x, b1.y, b1.z, b1.w};
            #pragma unroll
            for (int i = 0; i < 8; i++)
                #pragma unroll
                for (int j = 0; j < 8; j++)
                    acc[i][j] = fmaf(av[i], bv[j], acc[i][j]);
        }
        if (s + 1 < NSTEPS) {
            const int nb = buf ^ 1;
            float* p0 = &sA[nb][aC0 * 132 + aR0];
            p0[0] = ra0.x; p0[132] = ra0.y; p0[264] = ra0.z; p0[396] = ra0.w;
            float* p1 = &sA[nb][aC1 * 132 + aR1];
            p1[0] = ra1.x; p1[132] = ra1.y; p1[264] = ra1.z; p1[396] = ra1.w;
            *reinterpret_cast<float4*>(&sB[nb][bR0 * 128 + bC0]) = rb0;
            *reinterpret_cast<float4*>(&sB[nb][bR1 * 128 + bC1]) = rb1;
        }
        __syncthreads();
        buf ^= 1;
    }

    #pragma unroll
    for (int i = 0; i < 8; i++) {
        const int m  = m0 + (ty << 3) + i;
        const int bb = m >> 11;
        const int sq = m & (S_LEN - 1);
        #pragma unroll
        for (int j = 0; j < 8; j++) {
            const int n = n0 + (tx << 3) + j;
            const float val = acc[i][j] + bias[n];
            const int ns = n - (slice << 10);     // col within 1024 slice
            const int hh = ns >> 6, dd = ns & 63;
            out[((bb * NHEAD + hh) * S_LEN + sq) * DHEAD + dd] = val;
        }
    }
}

// =====================================================================
// Output projection GEMM: out = ctx[4096,1024] @ Wout[1024,1024] + bout.
// =====================================================================
__global__ __launch_bounds__(256, 2) void sgemm_out_kernel(
    const float* __restrict__ X, const float* __restrict__ W,
    const float* __restrict__ bias, float* __restrict__ out)
{
    __shared__ float sA[2][16 * 132];
    __shared__ float sB[2][16 * 128];

    const int tid = threadIdx.x;
    const int tx = tid & 15, ty = tid >> 4;
    const int m0 = blockIdx.y << 7;
    const int n0 = blockIdx.x << 7;
    const int ldw = E_DIM;

    const int aR0 = tid >> 2,         aC0 = (tid & 3) << 2;
    const int aR1 = (tid + 256) >> 2, aC1 = aC0;
    const int bR0 = tid >> 5,         bC0 = (tid & 31) << 2;
    const int bR1 = bR0 + 8,          bC1 = bC0;

    float acc[8][8];
    #pragma unroll
    for (int i = 0; i < 8; i++)
        #pragma unroll
        for (int j = 0; j < 8; j++) acc[i][j] = 0.f;

    float4 ra0, ra1, rb0, rb1;
    ra0 = *reinterpret_cast<const float4*>(&X[(m0 + aR0) * KDIM + aC0]);
    ra1 = *reinterpret_cast<const float4*>(&X[(m0 + aR1) * KDIM + aC1]);
    rb0 = *reinterpret_cast<const float4*>(&W[bR0 * ldw + n0 + bC0]);
    rb1 = *reinterpret_cast<const float4*>(&W[bR1 * ldw + n0 + bC1]);
    {
        float* p0 = &sA[0][aC0 * 132 + aR0];
        p0[0] = ra0.x; p0[132] = ra0.y; p0[264] = ra0.z; p0[396] = ra0.w;
        float* p1 = &sA[0][aC1 * 132 + aR1];
        p1[0] = ra1.x; p1[132] = ra1.y; p1[264] = ra1.z; p1[396] = ra1.w;
        *reinterpret_cast<float4*>(&sB[0][bR0 * 128 + bC0]) = rb0;
        *reinterpret_cast<float4*>(&sB[0][bR1 * 128 + bC1]) = rb1;
    }
    __syncthreads();

    int buf = 0;
    const int NSTEPS = KDIM / 16;
    for (int s = 0; s < NSTEPS; s++) {
        if (s + 1 < NSTEPS) {
            const int kn = (s + 1) << 4;
            ra0 = *reinterpret_cast<const float4*>(&X[(m0 + aR0) * KDIM + kn + aC0]);
            ra1 = *reinterpret_cast<const float4*>(&X[(m0 + aR1) * KDIM + kn + aC1]);
            rb0 = *reinterpret_cast<const float4*>(&W[(kn + bR0) * ldw + n0 + bC0]);
            rb1 = *reinterpret_cast<const float4*>(&W[(kn + bR1) * ldw + n0 + bC1]);
        }
        const float* pa = &sA[buf][ty << 3];
        const float* pb = &sB[buf][tx << 3];
        #pragma unroll 8
        for (int kk = 0; kk < 16; kk++) {
            float4 a0 = *reinterpret_cast<const float4*>(&pa[kk * 132]);
            float4 a1 = *reinterpret_cast<const float4*>(&pa[kk * 132 + 4]);
            float4 b0 = *reinterpret_cast<const float4*>(&pb[kk * 128]);
            float4 b1 = *reinterpret_cast<const float4*>(&pb[kk * 128 + 4]);
            float av[8] = {a0.x, a0.y, a0.z, a0.w, a1.x, a1.y, a1.z, a1.w};
            float bv[8] = {b0.x, b0.y, b0.z, b0.w, b1.x, b1.y, b1.z, b1.w};
            #pragma unroll
            for (int i = 0; i < 8; i++)
                #pragma unroll
                for (int j = 0; j < 8; j++)
                    acc[i][j] = fmaf(av[i], bv[j], acc[i][j]);
        }
        if (s + 1 < NSTEPS) {
            const int nb = buf ^ 1;
            float* p0 = &sA[nb][aC0 * 132 + aR0];
            p0[0] = ra0.x; p0[132] = ra0.y; p0[264] = ra0.z; p0[396] = ra0.w;
            float* p1 = &sA[nb][aC1 * 132 + aR1];
            p1[0] = ra1.x; p1[132] = ra1.y; p1[264] = ra1.z; p1[396] = ra1.w;
            *reinterpret_cast<float4*>(&sB[nb][bR0 * 128 + bC0]) = rb0;
            *reinterpret_cast<float4*>(&sB[nb][bR1 * 128 + bC1]) = rb1;
        }
        __syncthreads();
        buf ^= 1;
    }

    #pragma unroll
    for (int i = 0; i < 8; i++) {
        const int m = m0 + (ty << 3) + i;
        #pragma unroll
        for (int j = 0; j < 8; j++) {
            const int n = n0 + (tx << 3) + j;
            out[m * E_DIM + n] = acc[i][j] + bias[n];
        }
    }
}

// =====================================================================
// Flash attention v2: grid (S/128, H, B), 256 threads.
// Q-tile 128 x K-tile 64, 8x4 microtiles (32 S-accums + 32 O-accums).
// =====================================================================
#define PADQ 132
#define PADK 68
#define ATTN_SMEM ((2 * 64 * PADQ + 2 * 64 * PADK) * (int)sizeof(float))  // 102400

__global__ __launch_bounds__(256, 2) void attn_kernel(
    const float* __restrict__ Qp, const float* __restrict__ Kp,
    const float* __restrict__ Vp, const int* __restrict__ mask,
    float* __restrict__ ctx)
{
    extern __shared__ float smem[];
    float* Qt = smem;                               // [d][q] 64 x PADQ
    float* Ps = smem + 64 * PADQ;                   // [j][i] 64 x PADQ
    float* Kt = smem + 2 * 64 * PADQ;               // [d][j] 64 x PADK
    float* Vs = smem + 2 * 64 * PADQ + 64 * PADK;   // [j][d] 64 x PADK

    const int tid = threadIdx.x;
    const int tx = tid & 15, ty = tid >> 4;   // tx: 4 K-cols, ty: 8 Q-rows
    const int q0 = blockIdx.x << 7;
    const int h  = blockIdx.y, b = blockIdx.z;
    const int base = ((b * NHEAD + h) * S_LEN) * DHEAD;

    // stage Q transposed once: Qt[d][s], 128 rows
    {
        const int d = tid & 63, sg = (tid >> 6) << 5;
        #pragma unroll
        for (int blk = 0; blk < 32; blk += 4) {
            const int s = q0 + sg + blk;
            float t0 = Qp[base + (s + 0) * DHEAD + d];
            float t1 = Qp[base + (s + 1) * DHEAD + d];
            float t2 = Qp[base + (s + 2) * DHEAD + d];
            float t3 = Qp[base + (s + 3) * DHEAD + d];
            *reinterpret_cast<float4*>(&Qt[d * PADQ + sg + blk]) = make_float4(t0, t1, t2, t3);
        }
    }

    float o[8][4];
    #pragma unroll
    for (int i = 0; i < 8; i++) { o[i][0] = o[i][1] = o[i][2] = o[i][3] = 0.f; }
    float mrow[8], lrow[8];
    #pragma unroll
    for (int i = 0; i < 8; i++) { mrow[i] = -1e30f; lrow[i] = 0.f; }

    for (int kt = 0; kt < S_LEN / 64; kt++) {
        const int k0 = kt << 6;
        __syncthreads();  // previous readers of Kt/Vs/Ps done

        // stage K transposed
        {
            const int d = tid & 63, sg = (tid >> 6) << 4;
            #pragma unroll
            for (int blk = 0; blk < 16; blk += 4) {
                const int s = k0 + sg + blk;
                float t0 = Kp[base + (s + 0) * DHEAD + d];
                float t1 = Kp[base + (s + 1) * DHEAD + d];
                float t2 = Kp[base + (s + 2) * DHEAD + d];
                float t3 = Kp[base + (s + 3) * DHEAD + d];
                *reinterpret_cast<float4*>(&Kt[d * PADK + sg + blk]) = make_float4(t0, t1, t2, t3);
            }
        }
        // stage V natural
        #pragma unroll
        for (int r = 0; r < 4; r++) {
            const int idx = tid + (r << 8);
            const int srow = idx >> 4, c = (idx & 15) << 2;
            float4 vv = *reinterpret_cast<const float4*>(&Vp[base + (k0 + srow) * DHEAD + c]);
            *reinterpret_cast<float4*>(&Vs[srow * PADK + c]) = vv;
        }
        __syncthreads();

        // S = Q @ K^T, 8x4 microtile
        float sa[8][4];
        #pragma unroll
        for (int i = 0; i < 8; i++) { sa[i][0] = sa[i][1] = sa[i][2] = sa[i][3] = 0.f; }
        #pragma unroll 4
        for (int kk = 0; kk < 64; kk++) {
            float4 a0 = *reinterpret_cast<const float4*>(&Qt[kk * PADQ + (ty << 3)]);
            float4 a1 = *reinterpret_cast<const float4*>(&Qt[kk * PADQ + (ty << 3) + 4]);
            float4 bk = *reinterpret_cast<const float4*>(&Kt[kk * PADK + (tx << 2)]);
            float av[8] = {a0.x, a0.y, a0.z, a0.w, a1.x, a1.y, a1.z, a1.w};
            float bv[4] = {bk.x, bk.y, bk.z, bk.w};
            #pragma unroll
            for (int i = 0; i < 8; i++)
                #pragma unroll
                for (int j = 0; j < 4; j++)
                    sa[i][j] = fmaf(av[i], bv[j], sa[i][j]);
        }

        // mask + scale (1/sqrt(64) = 0.125)
        #pragma unroll
        for (int ii = 0; ii < 8; ii++) {
            const int4 mv = *reinterpret_cast<const int4*>(
                &mask[(q0 + (ty << 3) + ii) * S_LEN + k0 + (tx << 2)]);
            sa[ii][0] = mv.x ? sa[ii][0] * 0.125f : -1e30f;
            sa[ii][1] = mv.y ? sa[ii][1] * 0.125f : -1e30f;
            sa[ii][2] = mv.z ? sa[ii][2] * 0.125f : -1e30f;
            sa[ii][3] = mv.w ? sa[ii][3] * 0.125f : -1e30f;
        }

        // online softmax per row (row spread over 16 tx lanes)
        #pragma unroll
        for (int ii = 0; ii < 8; ii++) {
            float tm = fmaxf(fmaxf(sa[ii][0], sa[ii][1]), fmaxf(sa[ii][2], sa[ii][3]));
            tm = fmaxf(tm, __shfl_xor_sync(0xffffffffu, tm, 8));
            tm = fmaxf(tm, __shfl_xor_sync(0xffffffffu, tm, 4));
            tm = fmaxf(tm, __shfl_xor_sync(0xffffffffu, tm, 2));
            tm = fmaxf(tm, __shfl_xor_sync(0xffffffffu, tm, 1));
            const float mn = fmaxf(mrow[ii], tm);
            const float corr = __expf(mrow[ii] - mn);
            mrow[ii] = mn;
            float ps = 0.f;
            #pragma unroll
            for (int jj = 0; jj < 4; jj++) {
                sa[ii][jj] = __expf(sa[ii][jj] - mn);
                ps += sa[ii][jj];
            }
            ps += __shfl_xor_sync(0xffffffffu, ps, 8);
            ps += __shfl_xor_sync(0xffffffffu, ps, 4);
            ps += __shfl_xor_sync(0xffffffffu, ps, 2);
            ps += __shfl_xor_sync(0xffffffffu, ps, 1);
            lrow[ii] = lrow[ii] * corr + ps;
            o[ii][0] *= corr; o[ii][1] *= corr; o[ii][2] *= corr; o[ii][3] *= corr;
        }

        // store P transposed: Ps[j][i]
        #pragma unroll
        for (int jj = 0; jj < 4; jj++) {
            *reinterpret_cast<float4*>(&Ps[((tx << 2) + jj) * PADQ + (ty << 3)]) =
                make_float4(sa[0][jj], sa[1][jj], sa[2][jj], sa[3][jj]);
            *reinterpret_cast<float4*>(&Ps[((tx << 2) + jj) * PADQ + (ty << 3) + 4]) =
                make_float4(sa[4][jj], sa[5][jj], sa[6][jj], sa[7][jj]);
        }
        __syncthreads();

        // O += P @ V, 8x4 microtile
        #pragma unroll 4
        for (int kk = 0; kk < 64; kk++) {
            float4 p0 = *reinterpret_cast<const float4*>(&Ps[kk * PADQ + (ty << 3)]);
            float4 p1 = *reinterpret_cast<const float4*>(&Ps[kk * PADQ + (ty << 3) + 4]);
            float4 vv = *reinterpret_cast<const float4*>(&Vs[kk * PADK + (tx << 2)]);
            float pv[8] = {p0.x, p0.y, p0.z, p0.w, p1.x, p1.y, p1.z, p1.w};
            float vb[4] = {vv.x, vv.y, vv.z, vv.w};
            #pragma unroll
            for (int i = 0; i < 8; i++)
                #pragma unroll
                for (int j = 0; j < 4; j++)
                    o[i][j] = fmaf(pv[i], vb[j], o[i][j]);
        }
    }

    // normalize + write ctx [b][s][e], e = h*64 + d
    #pragma unroll
    for (int ii = 0; ii < 8; ii++) {
        const float inv = 1.f / lrow[ii];
        const int row = q0 + (ty << 3) + ii;
        float4 w = make_float4(o[ii][0] * inv, o[ii][1] * inv, o[ii][2] * inv, o[ii][3] * inv);
        *reinterpret_cast<float4*>(&ctx[(b * S_LEN + row) * E_DIM + h * DHEAD + (tx << 2)]) = w;
    }
}

// =====================================================================
extern "C" void kernel_launch(void* const* d_in, const int* in_sizes, int n_in,
                              void* d_out, int out_size)
{
    const float* q    = (const float*)d_in[0];
    const float* k    = (const float*)d_in[1];
    const float* v    = (const float*)d_in[2];
    const int*   mask = (const int*)  d_in[3];
    const float* Wqkv = (const float*)d_in[4];
    const float* bqkv = (const float*)d_in[5];
    const float* Wout = (const float*)d_in[6];
    const float* bout = (const float*)d_in[7];
    float* out = (float*)d_out;
    (void)in_sizes; (void)n_in; (void)out_size;

    float *Qp, *Kp, *Vp, *ctx;
    cudaGetSymbolAddress((void**)&Qp,  g_Qp);
    cudaGetSymbolAddress((void**)&Kp,  g_Kp);
    cudaGetSymbolAddress((void**)&Vp,  g_Vp);
    cudaGetSymbolAddress((void**)&ctx, g_ctx);

    cudaFuncSetAttribute(attn_kernel, cudaFuncAttributeMaxDynamicSharedMemorySize, ATTN_SMEM);

    // fused QKV projection: one launch, 768 blocks
    sgemm_qkv_kernel<<<dim3(24, MROWS / 128), 256>>>(q, k, v, Wqkv, bqkv, Qp, Kp, Vp);

    // flash attention
    attn_kernel<<<dim3(S_LEN / 128, NHEAD, BATCH), 256, ATTN_SMEM>>>(Qp, Kp, Vp, mask, ctx);

    // output projection
    sgemm_out_kernel<<<dim3(E_DIM / 128, MROWS / 128), 256>>>(ctx, Wout, bout, out);
}

// round 11
// speedup vs baseline: 1.0544x; 1.0002x over previous
#include <cuda_runtime.h>

#define S_LEN 2048
#define E_DIM 1024
#define NHEAD 16
#define DHEAD 64
#define BATCH 2
#define MROWS 4096   // BATCH * S_LEN
#define KDIM  1024

// ---------------- scratch (allocation-free) ----------------
__device__ float g_Qp[BATCH * NHEAD * S_LEN * DHEAD];  // [b][h][s][d]
__device__ float g_Kp[BATCH * NHEAD * S_LEN * DHEAD];
__device__ float g_Vp[BATCH * NHEAD * S_LEN * DHEAD];
__device__ float g_ctx[BATCH * S_LEN * E_DIM];         // [b][s][e]

// =====================================================================
// Fused QKV projection GEMM.
// grid (24, 32): blockIdx.x selects 128-col slab of the 3072-wide Wqkv;
// slice = bx>>3 picks input (q/k/v) and output buffer (Qp/Kp/Vp).
// 128x128 tile, BK=16, 256 threads, 8x8 microtile, double-buffered.
// Output written in head-split layout [b][h][s][d].
// =====================================================================
__global__ __launch_bounds__(256, 2) void sgemm_qkv_kernel(
    const float* __restrict__ q, const float* __restrict__ k,
    const float* __restrict__ v, const float* __restrict__ W,
    const float* __restrict__ bias,
    float* __restrict__ Qp, float* __restrict__ Kp, float* __restrict__ Vp)
{
    __shared__ float sA[2][16 * 132];
    __shared__ float sB[2][16 * 128];

    const int tid = threadIdx.x;
    const int tx = tid & 15, ty = tid >> 4;
    const int m0 = blockIdx.y << 7;
    const int bx = blockIdx.x;
    const int slice = bx >> 3;
    const int n0 = bx << 7;                 // global col into [0,3072)
    const int ldw = 3 * E_DIM;

    const float* X  = (slice == 0) ? q : (slice == 1) ? k : v;
    float* out      = (slice == 0) ? Qp : (slice == 1) ? Kp : Vp;

    const int aR0 = tid >> 2,         aC0 = (tid & 3) << 2;
    const int aR1 = (tid + 256) >> 2, aC1 = aC0;
    const int bR0 = tid >> 5,         bC0 = (tid & 31) << 2;
    const int bR1 = bR0 + 8,          bC1 = bC0;

    float acc[8][8];
    #pragma unroll
    for (int i = 0; i < 8; i++)
        #pragma unroll
        for (int j = 0; j < 8; j++) acc[i][j] = 0.f;

    float4 ra0, ra1, rb0, rb1;
    ra0 = *reinterpret_cast<const float4*>(&X[(m0 + aR0) * KDIM + aC0]);
    ra1 = *reinterpret_cast<const float4*>(&X[(m0 + aR1) * KDIM + aC1]);
    rb0 = *reinterpret_cast<const float4*>(&W[bR0 * ldw + n0 + bC0]);
    rb1 = *reinterpret_cast<const float4*>(&W[bR1 * ldw + n0 + bC1]);
    {
        float* p0 = &sA[0][aC0 * 132 + aR0];
        p0[0] = ra0.x; p0[132] = ra0.y; p0[264] = ra0.z; p0[396] = ra0.w;
        float* p1 = &sA[0][aC1 * 132 + aR1];
        p1[0] = ra1.x; p1[132] = ra1.y; p1[264] = ra1.z; p1[396] = ra1.w;
        *reinterpret_cast<float4*>(&sB[0][bR0 * 128 + bC0]) = rb0;
        *reinterpret_cast<float4*>(&sB[0][bR1 * 128 + bC1]) = rb1;
    }
    __syncthreads();

    int buf = 0;
    const int NSTEPS = KDIM / 16;
    for (int s = 0; s < NSTEPS; s++) {
        if (s + 1 < NSTEPS) {
            const int kn = (s + 1) << 4;
            ra0 = *reinterpret_cast<const float4*>(&X[(m0 + aR0) * KDIM + kn + aC0]);
            ra1 = *reinterpret_cast<const float4*>(&X[(m0 + aR1) * KDIM + kn + aC1]);
            rb0 = *reinterpret_cast<const float4*>(&W[(kn + bR0) * ldw + n0 + bC0]);
            rb1 = *reinterpret_cast<const float4*>(&W[(kn + bR1) * ldw + n0 + bC1]);
        }
        const float* pa = &sA[buf][ty << 3];
        const float* pb = &sB[buf][tx << 3];
        #pragma unroll 8
        for (int kk = 0; kk < 16; kk++) {
            float4 a0 = *reinterpret_cast<const float4*>(&pa[kk * 132]);
            float4 a1 = *reinterpret_cast<const float4*>(&pa[kk * 132 + 4]);
            float4 b0 = *reinterpret_cast<const float4*>(&pb[kk * 128]);
            float4 b1 = *reinterpret_cast<const float4*>(&pb[kk * 128 + 4]);
            float av[8] = {a0.x, a0.y, a0.z, a0.w, a1.x, a1.y, a1.z, a1.w};
            float bv[8] = {b0.x, b0.y, b0.z, b0.w, b1.x, b1.y, b1.z, b1.w};
            #pragma unroll
            for (int i = 0; i < 8; i++)
                #pragma unroll
                for (int j = 0; j < 8; j++)
                    acc[i][j] = fmaf(av[i], bv[j], acc[i][j]);
        }
        if (s + 1 < NSTEPS) {
            const int nb = buf ^ 1;
            float* p0 = &sA[nb][aC0 * 132 + aR0];
            p0[0] = ra0.x; p0[132] = ra0.y; p0[264] = ra0.z; p0[396] = ra0.w;
            float* p1 = &sA[nb][aC1 * 132 + aR1];
            p1[0] = ra1.x; p1[132] = ra1.y; p1[264] = ra1.z; p1[396] = ra1.w;
            *reinterpret_cast<float4*>(&sB[nb][bR0 * 128 + bC0]) = rb0;
            *reinterpret_cast<float4*>(&sB[nb][bR1 * 128 + bC1]) = rb1;
        }
        __syncthreads();
        buf ^= 1;
    }

    #pragma unroll
    for (int i = 0; i < 8; i++) {
        const int m  = m0 + (ty << 3) + i;
        const int bb = m >> 11;
        const int sq = m & (S_LEN - 1);
        #pragma unroll
        for (int j = 0; j < 8; j++) {
            const int n = n0 + (tx << 3) + j;
            const float val = acc[i][j] + bias[n];
            const int ns = n - (slice << 10);     // col within 1024 slice
            const int hh = ns >> 6, dd = ns & 63;
            out[((bb * NHEAD + hh) * S_LEN + sq) * DHEAD + dd] = val;
        }
    }
}

// =====================================================================
// Output projection GEMM: out = ctx[4096,1024] @ Wout[1024,1024] + bout.
// =====================================================================
__global__ __launch_bounds__(256, 2) void sgemm_out_kernel(
    const float* __restrict__ X, const float* __restrict__ W,
    const float* __restrict__ bias, float* __restrict__ out)
{
    __shared__ float sA[2][16 * 132];
    __shared__ float sB[2][16 * 128];

    const int tid = threadIdx.x;
    const int tx = tid & 15, ty = tid >> 4;
    const int m0 = blockIdx.y << 7;
    const int n0 = blockIdx.x << 7;
    const int ldw = E_DIM;

    const int aR0 = tid >> 2,         aC0 = (tid & 3) << 2;
    const int aR1 = (tid + 256) >> 2, aC1 = aC0;
    const int bR0 = tid >> 5,         bC0 = (tid & 31) << 2;
    const int bR1 = bR0 + 8,          bC1 = bC0;

    float acc[8][8];
    #pragma unroll
    for (int i = 0; i < 8; i++)
        #pragma unroll
        for (int j = 0; j < 8; j++) acc[i][j] = 0.f;

    float4 ra0, ra1, rb0, rb1;
    ra0 = *reinterpret_cast<const float4*>(&X[(m0 + aR0) * KDIM + aC0]);
    ra1 = *reinterpret_cast<const float4*>(&X[(m0 + aR1) * KDIM + aC1]);
    rb0 = *reinterpret_cast<const float4*>(&W[bR0 * ldw + n0 + bC0]);
    rb1 = *reinterpret_cast<const float4*>(&W[bR1 * ldw + n0 + bC1]);
    {
        float* p0 = &sA[0][aC0 * 132 + aR0];
        p0[0] = ra0.x; p0[132] = ra0.y; p0[264] = ra0.z; p0[396] = ra0.w;
        float* p1 = &sA[0][aC1 * 132 + aR1];
        p1[0] = ra1.x; p1[132] = ra1.y; p1[264] = ra1.z; p1[396] = ra1.w;
        *reinterpret_cast<float4*>(&sB[0][bR0 * 128 + bC0]) = rb0;
        *reinterpret_cast<float4*>(&sB[0][bR1 * 128 + bC1]) = rb1;
    }
    __syncthreads();

    int buf = 0;
    const int NSTEPS = KDIM / 16;
    for (int s = 0; s < NSTEPS; s++) {
        if (s + 1 < NSTEPS) {
            const int kn = (s + 1) << 4;
            ra0 = *reinterpret_cast<const float4*>(&X[(m0 + aR0) * KDIM + kn + aC0]);
            ra1 = *reinterpret_cast<const float4*>(&X[(m0 + aR1) * KDIM + kn + aC1]);
            rb0 = *reinterpret_cast<const float4*>(&W[(kn + bR0) * ldw + n0 + bC0]);
            rb1 = *reinterpret_cast<const float4*>(&W[(kn + bR1) * ldw + n0 + bC1]);
        }
        const float* pa = &sA[buf][ty << 3];
        const float* pb = &sB[buf][tx << 3];
        #pragma unroll 8
        for (int kk = 0; kk < 16; kk++) {
            float4 a0 = *reinterpret_cast<const float4*>(&pa[kk * 132]);
            float4 a1 = *reinterpret_cast<const float4*>(&pa[kk * 132 + 4]);
            float4 b0 = *reinterpret_cast<const float4*>(&pb[kk * 128]);
            float4 b1 = *reinterpret_cast<const float4*>(&pb[kk * 128 + 4]);
            float av[8] = {a0.x, a0.y, a0.z, a0.w, a1.x, a1.y, a1.z, a1.w};
            float bv[8] = {b0.x, b0.y, b0.z, b0.w, b1.x, b1.y, b1.z, b1.w};
            #pragma unroll
            for (int i = 0; i < 8; i++)
                #pragma unroll
                for (int j = 0; j < 8; j++)
                    acc[i][j] = fmaf(av[i], bv[j], acc[i][j]);
        }
        if (s + 1 < NSTEPS) {
            const int nb = buf ^ 1;
            float* p0 = &sA[nb][aC0 * 132 + aR0];
            p0[0] = ra0.x; p0[132] = ra0.y; p0[264] = ra0.z; p0[396] = ra0.w;
            float* p1 = &sA[nb][aC1 * 132 + aR1];
            p1[0] = ra1.x; p1[132] = ra1.y; p1[264] = ra1.z; p1[396] = ra1.w;
            *reinterpret_cast<float4*>(&sB[nb][bR0 * 128 + bC0]) = rb0;
            *reinterpret_cast<float4*>(&sB[nb][bR1 * 128 + bC1]) = rb1;
        }
        __syncthreads();
        buf ^= 1;
    }

    #pragma unroll
    for (int i = 0; i < 8; i++) {
        const int m = m0 + (ty << 3) + i;
        #pragma unroll
        for (int j = 0; j < 8; j++) {
            const int n = n0 + (tx << 3) + j;
            out[m * E_DIM + n] = acc[i][j] + bias[n];
        }
    }
}

// =====================================================================
// Flash attention v2: grid (S/128, H, B), 256 threads.
// Q-tile 128 x K-tile 64, 8x4 microtiles (32 S-accums + 32 O-accums).
// =====================================================================
#define PADQ 132
#define PADK 68
#define ATTN_SMEM ((2 * 64 * PADQ + 2 * 64 * PADK) * (int)sizeof(float))  // 102400

__global__ __launch_bounds__(256, 2) void attn_kernel(
    const float* __restrict__ Qp, const float* __restrict__ Kp,
    const float* __restrict__ Vp, const int* __restrict__ mask,
    float* __restrict__ ctx)
{
    extern __shared__ float smem[];
    float* Qt = smem;                               // [d][q] 64 x PADQ
    float* Ps = smem + 64 * PADQ;                   // [j][i] 64 x PADQ
    float* Kt = smem + 2 * 64 * PADQ;               // [d][j] 64 x PADK
    float* Vs = smem + 2 * 64 * PADQ + 64 * PADK;   // [j][d] 64 x PADK

    const int tid = threadIdx.x;
    const int tx = tid & 15, ty = tid >> 4;   // tx: 4 K-cols, ty: 8 Q-rows
    const int q0 = blockIdx.x << 7;
    const int h  = blockIdx.y, b = blockIdx.z;
    const int base = ((b * NHEAD + h) * S_LEN) * DHEAD;

    // stage Q transposed once: Qt[d][s], 128 rows
    {
        const int d = tid & 63, sg = (tid >> 6) << 5;
        #pragma unroll
        for (int blk = 0; blk < 32; blk += 4) {
            const int s = q0 + sg + blk;
            float t0 = Qp[base + (s + 0) * DHEAD + d];
            float t1 = Qp[base + (s + 1) * DHEAD + d];
            float t2 = Qp[base + (s + 2) * DHEAD + d];
            float t3 = Qp[base + (s + 3) * DHEAD + d];
            *reinterpret_cast<float4*>(&Qt[d * PADQ + sg + blk]) = make_float4(t0, t1, t2, t3);
        }
    }

    float o[8][4];
    #pragma unroll
    for (int i = 0; i < 8; i++) { o[i][0] = o[i][1] = o[i][2] = o[i][3] = 0.f; }
    float mrow[8], lrow[8];
    #pragma unroll
    for (int i = 0; i < 8; i++) { mrow[i] = -1e30f; lrow[i] = 0.f; }

    for (int kt = 0; kt < S_LEN / 64; kt++) {
        const int k0 = kt << 6;
        __syncthreads();  // previous readers of Kt/Vs/Ps done

        // stage K transposed
        {
            const int d = tid & 63, sg = (tid >> 6) << 4;
            #pragma unroll
            for (int blk = 0; blk < 16; blk += 4) {
                const int s = k0 + sg + blk;
                float t0 = Kp[base + (s + 0) * DHEAD + d];
                float t1 = Kp[base + (s + 1) * DHEAD + d];
                float t2 = Kp[base + (s + 2) * DHEAD + d];
                float t3 = Kp[base + (s + 3) * DHEAD + d];
                *reinterpret_cast<float4*>(&Kt[d * PADK + sg + blk]) = make_float4(t0, t1, t2, t3);
            }
        }
        // stage V natural
        #pragma unroll
        for (int r = 0; r < 4; r++) {
            const int idx = tid + (r << 8);
            const int srow = idx >> 4, c = (idx & 15) << 2;
            float4 vv = *reinterpret_cast<const float4*>(&Vp[base + (k0 + srow) * DHEAD + c]);
            *reinterpret_cast<float4*>(&Vs[srow * PADK + c]) = vv;
        }
        __syncthreads();

        // S = Q @ K^T, 8x4 microtile
        float sa[8][4];
        #pragma unroll
        for (int i = 0; i < 8; i++) { sa[i][0] = sa[i][1] = sa[i][2] = sa[i][3] = 0.f; }
        #pragma unroll 4
        for (int kk = 0; kk < 64; kk++) {
            float4 a0 = *reinterpret_cast<const float4*>(&Qt[kk * PADQ + (ty << 3)]);
            float4 a1 = *reinterpret_cast<const float4*>(&Qt[kk * PADQ + (ty << 3) + 4]);
            float4 bk = *reinterpret_cast<const float4*>(&Kt[kk * PADK + (tx << 2)]);
            float av[8] = {a0.x, a0.y, a0.z, a0.w, a1.x, a1.y, a1.z, a1.w};
            float bv[4] = {bk.x, bk.y, bk.z, bk.w};
            #pragma unroll
            for (int i = 0; i < 8; i++)
                #pragma unroll
                for (int j = 0; j < 4; j++)
                    sa[i][j] = fmaf(av[i], bv[j], sa[i][j]);
        }

        // mask + scale (1/sqrt(64) = 0.125)
        #pragma unroll
        for (int ii = 0; ii < 8; ii++) {
            const int4 mv = *reinterpret_cast<const int4*>(
                &mask[(q0 + (ty << 3) + ii) * S_LEN + k0 + (tx << 2)]);
            sa[ii][0] = mv.x ? sa[ii][0] * 0.125f : -1e30f;
            sa[ii][1] = mv.y ? sa[ii][1] * 0.125f : -1e30f;
            sa[ii][2] = mv.z ? sa[ii][2] * 0.125f : -1e30f;
            sa[ii][3] = mv.w ? sa[ii][3] * 0.125f : -1e30f;
        }

        // online softmax per row (row spread over 16 tx lanes)
        #pragma unroll
        for (int ii = 0; ii < 8; ii++) {
            float tm = fmaxf(fmaxf(sa[ii][0], sa[ii][1]), fmaxf(sa[ii][2], sa[ii][3]));
            tm = fmaxf(tm, __shfl_xor_sync(0xffffffffu, tm, 8));
            tm = fmaxf(tm, __shfl_xor_sync(0xffffffffu, tm, 4));
            tm = fmaxf(tm, __shfl_xor_sync(0xffffffffu, tm, 2));
            tm = fmaxf(tm, __shfl_xor_sync(0xffffffffu, tm, 1));
            const float mn = fmaxf(mrow[ii], tm);
            const float corr = __expf(mrow[ii] - mn);
            mrow[ii] = mn;
            float ps = 0.f;
            #pragma unroll
            for (int jj = 0; jj < 4; jj++) {
                sa[ii][jj] = __expf(sa[ii][jj] - mn);
                ps += sa[ii][jj];
            }
            ps += __shfl_xor_sync(0xffffffffu, ps, 8);
            ps += __shfl_xor_sync(0xffffffffu, ps, 4);
            ps += __shfl_xor_sync(0xffffffffu, ps, 2);
            ps += __shfl_xor_sync(0xffffffffu, ps, 1);
            lrow[ii] = lrow[ii] * corr + ps;
            o[ii][0] *= corr; o[ii][1] *= corr; o[ii][2] *= corr; o[ii][3] *= corr;
        }

        // store P transposed: Ps[j][i]
        #pragma unroll
        for (int jj = 0; jj < 4; jj++) {
            *reinterpret_cast<float4*>(&Ps[((tx << 2) + jj) * PADQ + (ty << 3)]) =
                make_float4(sa[0][jj], sa[1][jj], sa[2][jj], sa[3][jj]);
            *reinterpret_cast<float4*>(&Ps[((tx << 2) + jj) * PADQ + (ty << 3) + 4]) =
                make_float4(sa[4][jj], sa[5][jj], sa[6][jj], sa[7][jj]);
        }
        __syncthreads();

        // O += P @ V, 8x4 microtile
        #pragma unroll 4
        for (int kk = 0; kk < 64; kk++) {
            float4 p0 = *reinterpret_cast<const float4*>(&Ps[kk * PADQ + (ty << 3)]);
            float4 p1 = *reinterpret_cast<const float4*>(&Ps[kk * PADQ + (ty << 3) + 4]);
            float4 vv = *reinterpret_cast<const float4*>(&Vs[kk * PADK + (tx << 2)]);
            float pv[8] = {p0.x, p0.y, p0.z, p0.w, p1.x, p1.y, p1.z, p1.w};
            float vb[4] = {vv.x, vv.y, vv.z, vv.w};
            #pragma unroll
            for (int i = 0; i < 8; i++)
                #pragma unroll
                for (int j = 0; j < 4; j++)
                    o[i][j] = fmaf(pv[i], vb[j], o[i][j]);
        }
    }

    // normalize + write ctx [b][s][e], e = h*64 + d
    #pragma unroll
    for (int ii = 0; ii < 8; ii++) {
        const float inv = 1.f / lrow[ii];
        const int row = q0 + (ty << 3) + ii;
        float4 w = make_float4(o[ii][0] * inv, o[ii][1] * inv, o[ii][2] * inv, o[ii][3] * inv);
        *reinterpret_cast<float4*>(&ctx[(b * S_LEN + row) * E_DIM + h * DHEAD + (tx << 2)]) = w;
    }
}

// =====================================================================
extern "C" void kernel_launch(void* const* d_in, const int* in_sizes, int n_in,
                              void* d_out, int out_size)
{
    const float* q    = (const float*)d_in[0];
    const float* k    = (const float*)d_in[1];
    const float* v    = (const float*)d_in[2];
    const int*   mask = (const int*)  d_in[3];
    const float* Wqkv = (const float*)d_in[4];
    const float* bqkv = (const float*)d_in[5];
    const float* Wout = (const float*)d_in[6];
    const float* bout = (const float*)d_in[7];
    float* out = (float*)d_out;
    (void)in_sizes; (void)n_in; (void)out_size;

    float *Qp, *Kp, *Vp, *ctx;
    cudaGetSymbolAddress((void**)&Qp,  g_Qp);
    cudaGetSymbolAddress((void**)&Kp,  g_Kp);
    cudaGetSymbolAddress((void**)&Vp,  g_Vp);
    cudaGetSymbolAddress((void**)&ctx, g_ctx);

    cudaFuncSetAttribute(attn_kernel, cudaFuncAttributeMaxDynamicSharedMemorySize, ATTN_SMEM);

    // fused QKV projection: one launch, 768 blocks
    sgemm_qkv_kernel<<<dim3(24, MROWS / 128), 256>>>(q, k, v, Wqkv, bqkv, Qp, Kp, Vp);

    // flash attention
    attn_kernel<<<dim3(S_LEN / 128, NHEAD, BATCH), 256, ATTN_SMEM>>>(Qp, Kp, Vp, mask, ctx);

    // output projection
    sgemm_out_kernel<<<dim3(E_DIM / 128, MROWS / 128), 256>>>(ctx, Wout, bout, out);
}